// round 10
// baseline (speedup 1.0000x reference)
#include <cuda_runtime.h>
#include <cstdint>

#define FDIM   1024
#define FV     256            // float4 per row
#define DDOM   8
#define MAXN   16384
#define NSEG   296            // 2 full waves on 148 SMs
#define MAXR   64             // max rows per segment (56)
#define SDEP   16             // stats cp.async depth (rows in flight)
#define ADEP   12             // apply cp.async depth
#define EPSV   1e-5f

// ---------------- scratch ----------------
__device__ float g_P[NSEG * DDOM * FDIM];     // partial sum(x)
__device__ float g_Q[NSEG * DDOM * FDIM];     // partial sum(x*x)
__device__ int   g_c[NSEG * DDOM];            // per-seg domain counts
__device__ unsigned char g_ydom[MAXN];        // decoded domain per row
__device__ float g_A[DDOM * FDIM];            // gamma * inv
__device__ float g_B[DDOM * FDIM];            // beta - mean * gamma * inv

// int64-vs-int32 y detection (odd 32-bit words all zero over 32 values)
__device__ __forceinline__ int detect64(const int* __restrict__ y) {
    const int4* p = (const int4*)y;
    int acc = 0;
#pragma unroll
    for (int i = 0; i < 8; i++) { int4 a = p[i]; acc |= a.y | a.w; }
    return acc == 0;
}

#define ACCUM(v)                                        \
    s1.x += v.x; s1.y += v.y; s1.z += v.z; s1.w += v.w; \
    s2.x = fmaf(v.x, v.x, s2.x);                        \
    s2.y = fmaf(v.y, v.y, s2.y);                        \
    s2.z = fmaf(v.z, v.z, s2.z);                        \
    s2.w = fmaf(v.w, v.w, s2.w);

#define CPA_ISSUE(slotbase, k, DEP) do {                                     \
        uint32_t _da = (slotbase) + ((k) % (DEP)) * 4096 + myoff;            \
        const void* _g = xb + ((size_t)(flat[(k)] + tid) << 4);              \
        asm volatile("cp.async.cg.shared.global [%0], [%1], 16;"             \
                     :: "r"(_da), "l"(_g) : "memory");                       \
        asm volatile("cp.async.commit_group;" ::: "memory");                 \
    } while (0)

// ---- K1: stats via deep cp.async pipeline over domain-sorted flat list ----
__global__ __launch_bounds__(256, 2)
void stats_k(const float4* __restrict__ x4, const int* __restrict__ yi,
             int n, int rlo, int rem) {
    __shared__ float4 buf[SDEP][256];    // 64 KB ring
    __shared__ int flat[MAXR];           // row*FV, domain-sorted
    __shared__ int cnt[DDOM];
    __shared__ int fill[DDOM];

    const int tid  = threadIdx.x;
    const int b    = blockIdx.x;
    const int base = b * rlo + min(b, rem);
    const int nr   = min(rlo + (b < rem ? 1 : 0), n - base);

    if (tid < DDOM) cnt[tid] = 0;
    __syncthreads();

    if (tid < 32) {   // warp 0: deterministic 2-tile counting sort -> flat[]
        const int is64 = detect64(yi);
        const int r0 = base + tid;
        const int r1 = base + 32 + tid;
        const int da = (tid < nr)      ? (is64 ? yi[2 * r0] : yi[r0]) : -1;
        const int db = (32 + tid < nr) ? (is64 ? yi[2 * r1] : yi[r1]) : -1;
        const unsigned ma = __match_any_sync(0xffffffffu, da);
        if (da >= 0) {
            g_ydom[r0] = (unsigned char)da;
            if ((int)(__ffs(ma) - 1) == tid) cnt[da] = __popc(ma);
        }
        __syncwarp();
        const unsigned mb = __match_any_sync(0xffffffffu, db);
        if (db >= 0) {
            g_ydom[r1] = (unsigned char)db;
            if ((int)(__ffs(mb) - 1) == tid) cnt[db] += __popc(mb);
        }
        __syncwarp();
        if (tid == 0) {
            int run = 0;
#pragma unroll
            for (int d = 0; d < DDOM; d++) { fill[d] = run; run += cnt[d]; }
        }
        __syncwarp();
        const int ra = __popc(ma & ((1u << tid) - 1u));
        if (da >= 0) flat[fill[da] + ra] = r0 * FV;
        __syncwarp();
        if (da >= 0 && (int)(__ffs(ma) - 1) == tid) fill[da] += __popc(ma);
        __syncwarp();
        const int rb = __popc(mb & ((1u << tid) - 1u));
        if (db >= 0) flat[fill[db] + rb] = r1 * FV;
    }
    __syncthreads();

    uint32_t sbuf;
    asm("{ .reg .u64 t; cvta.to.shared.u64 t, %1; cvt.u32.u64 %0, t; }"
        : "=r"(sbuf) : "l"(buf));
    const char* xb = (const char*)x4;
    const uint32_t myoff = tid * 16;

    const int np = min(SDEP, nr);
    for (int k = 0; k < np; k++) CPA_ISSUE(sbuf, k, SDEP);
    int issued = np;
    int i = 0;

#pragma unroll
    for (int d = 0; d < DDOM; d++) {
        const int nd = cnt[d];
        float4 s1 = make_float4(0.f, 0.f, 0.f, 0.f);
        float4 s2 = make_float4(0.f, 0.f, 0.f, 0.f);
        for (int k = 0; k < nd; k++, i++) {
            if (issued < nr) {
                asm volatile("cp.async.wait_group %0;" :: "n"(SDEP - 1) : "memory");
            } else {
                asm volatile("cp.async.wait_group 0;" ::: "memory");
            }
            float4 v = buf[i % SDEP][tid];
            if (issued < nr) { CPA_ISSUE(sbuf, issued, SDEP); issued++; }
            ACCUM(v);
        }
        const size_t o = ((size_t)b * DDOM + d) * FV + tid;
        ((float4*)g_P)[o] = s1;
        ((float4*)g_Q)[o] = s2;
    }
    if (tid < DDOM) g_c[b * DDOM + tid] = cnt[tid];
}

// ---- K2: fold segments -> A/B. grid = 64 blocks (8 dom x 8 f4-slices). ----
__global__ __launch_bounds__(256)
void finalize_k(const float* __restrict__ gamma, const float* __restrict__ beta,
                int nseg) {
    __shared__ float4 smP[8][32];
    __shared__ float4 smQ[8][32];
    __shared__ int    scnt[256];
    const int tid  = threadIdx.x;
    const int d    = blockIdx.x >> 3;
    const int fs   = blockIdx.x & 7;
    const int w    = tid >> 5, lane = tid & 31;
    const int posIdx = fs * 32 + lane;

    {
        int c = 0;
        for (int s = tid; s < nseg; s += 256) c += g_c[s * DDOM + d];
        scnt[tid] = c;
    }

    const float4* P4 = (const float4*)g_P;
    const float4* Q4 = (const float4*)g_Q;
    float4 ap = make_float4(0.f, 0.f, 0.f, 0.f);
    float4 aq = make_float4(0.f, 0.f, 0.f, 0.f);
    int s = w;
    for (; s + 8 < nseg; s += 16) {
        const size_t o0 = ((size_t)s * DDOM + d) * FV + posIdx;
        const size_t o1 = ((size_t)(s + 8) * DDOM + d) * FV + posIdx;
        float4 p0 = P4[o0], q0 = Q4[o0];
        float4 p1 = P4[o1], q1 = Q4[o1];
        ap.x += p0.x + p1.x; ap.y += p0.y + p1.y;
        ap.z += p0.z + p1.z; ap.w += p0.w + p1.w;
        aq.x += q0.x + q1.x; aq.y += q0.y + q1.y;
        aq.z += q0.z + q1.z; aq.w += q0.w + q1.w;
    }
    for (; s < nseg; s += 8) {
        const size_t o = ((size_t)s * DDOM + d) * FV + posIdx;
        float4 p = P4[o], q = Q4[o];
        ap.x += p.x; ap.y += p.y; ap.z += p.z; ap.w += p.w;
        aq.x += q.x; aq.y += q.y; aq.z += q.z; aq.w += q.w;
    }
    smP[w][lane] = ap;
    smQ[w][lane] = aq;
    __syncthreads();

    for (int off = 128; off > 0; off >>= 1) {
        if (tid < off) scnt[tid] += scnt[tid + off];
        __syncthreads();
    }
    const float c = (float)scnt[0];

    if (w == 0) {
        float4 s1 = smP[0][lane], s2 = smQ[0][lane];
#pragma unroll
        for (int ww = 1; ww < 8; ww++) {
            float4 p = smP[ww][lane], q = smQ[ww][lane];
            s1.x += p.x; s1.y += p.y; s1.z += p.z; s1.w += p.w;
            s2.x += q.x; s2.y += q.y; s2.z += q.z; s2.w += q.w;
        }
        const int o = d * FDIM + posIdx * 4;
        float4 A, Bv;
        if (c > 1.5f) {
            const float rc = 1.0f / c;
            float4 g  = *(const float4*)(gamma + o);
            float4 be = *(const float4*)(beta + o);
            float mx = s1.x * rc, my = s1.y * rc, mz = s1.z * rc, mw = s1.w * rc;
            float vx = fmaf(-mx, mx, s2.x * rc);
            float vy = fmaf(-my, my, s2.y * rc);
            float vz = fmaf(-mz, mz, s2.z * rc);
            float vw = fmaf(-mw, mw, s2.w * rc);
            A.x = g.x * rsqrtf(vx + EPSV);
            A.y = g.y * rsqrtf(vy + EPSV);
            A.z = g.z * rsqrtf(vz + EPSV);
            A.w = g.w * rsqrtf(vw + EPSV);
            Bv.x = fmaf(-mx, A.x, be.x);
            Bv.y = fmaf(-my, A.y, be.y);
            Bv.z = fmaf(-mz, A.z, be.z);
            Bv.w = fmaf(-mw, A.w, be.w);
        } else if (c > 0.5f) {   // single-sample domain: out = x
            A  = make_float4(1.f, 1.f, 1.f, 1.f);
            Bv = make_float4(0.f, 0.f, 0.f, 0.f);
        } else {                 // empty domain (unused)
            A  = make_float4(0.f, 0.f, 0.f, 0.f);
            Bv = make_float4(0.f, 0.f, 0.f, 0.f);
        }
        *(float4*)(g_A + o) = A;
        *(float4*)(g_B + o) = Bv;
    }
}

// ---- K3: apply via cp.async pipeline, domain-sorted, A/B once per domain ----
__global__ __launch_bounds__(256, 2)
void apply_k(const float4* __restrict__ x4, float4* __restrict__ o4,
             int n, int rlo, int rem) {
    __shared__ float4 buf[ADEP][256];    // 48 KB ring
    __shared__ int flat[MAXR];
    __shared__ int cnt[DDOM];
    __shared__ int fill[DDOM];

    const int tid  = threadIdx.x;
    const int b    = blockIdx.x;
    const int base = b * rlo + min(b, rem);
    const int nr   = min(rlo + (b < rem ? 1 : 0), n - base);

    if (tid < DDOM) cnt[tid] = 0;
    __syncthreads();

    if (tid < 32) {   // warp 0: sort by cached domains
        const int r0 = base + tid;
        const int r1 = base + 32 + tid;
        const int da = (tid < nr)      ? (int)g_ydom[r0] : -1;
        const int db = (32 + tid < nr) ? (int)g_ydom[r1] : -1;
        const unsigned ma = __match_any_sync(0xffffffffu, da);
        if (da >= 0 && (int)(__ffs(ma) - 1) == tid) cnt[da] = __popc(ma);
        __syncwarp();
        const unsigned mb = __match_any_sync(0xffffffffu, db);
        if (db >= 0 && (int)(__ffs(mb) - 1) == tid) cnt[db] += __popc(mb);
        __syncwarp();
        if (tid == 0) {
            int run = 0;
#pragma unroll
            for (int d = 0; d < DDOM; d++) { fill[d] = run; run += cnt[d]; }
        }
        __syncwarp();
        const int ra = __popc(ma & ((1u << tid) - 1u));
        if (da >= 0) flat[fill[da] + ra] = r0 * FV;
        __syncwarp();
        if (da >= 0 && (int)(__ffs(ma) - 1) == tid) fill[da] += __popc(ma);
        __syncwarp();
        const int rb = __popc(mb & ((1u << tid) - 1u));
        if (db >= 0) flat[fill[db] + rb] = r1 * FV;
    }
    __syncthreads();

    uint32_t sbuf;
    asm("{ .reg .u64 t; cvta.to.shared.u64 t, %1; cvt.u32.u64 %0, t; }"
        : "=r"(sbuf) : "l"(buf));
    const char* xb = (const char*)x4;
    const uint32_t myoff = tid * 16;

    const int np = min(ADEP, nr);
    for (int k = 0; k < np; k++) CPA_ISSUE(sbuf, k, ADEP);
    int issued = np;
    int i = 0;

    const float4* A4 = (const float4*)g_A;
    const float4* B4 = (const float4*)g_B;

#pragma unroll
    for (int d = 0; d < DDOM; d++) {
        const int nd = cnt[d];
        if (nd == 0) continue;
        const float4 a  = __ldg(A4 + d * FV + tid);
        const float4 bb = __ldg(B4 + d * FV + tid);
        for (int k = 0; k < nd; k++, i++) {
            if (issued < nr) {
                asm volatile("cp.async.wait_group %0;" :: "n"(ADEP - 1) : "memory");
            } else {
                asm volatile("cp.async.wait_group 0;" ::: "memory");
            }
            float4 v = buf[i % ADEP][tid];
            const int ro = flat[i];
            if (issued < nr) { CPA_ISSUE(sbuf, issued, ADEP); issued++; }
            float4 w;
            w.x = fmaf(v.x, a.x, bb.x);
            w.y = fmaf(v.y, a.y, bb.y);
            w.z = fmaf(v.z, a.z, bb.z);
            w.w = fmaf(v.w, a.w, bb.w);
            __stcs(o4 + ro + tid, w);
        }
    }
}

extern "C" void kernel_launch(void* const* d_in, const int* in_sizes, int n_in,
                              void* d_out, int out_size) {
    const float* x     = (const float*)d_in[0];
    const int*   y     = (const int*)d_in[1];
    const float* gamma = (const float*)d_in[2];
    const float* beta  = (const float*)d_in[3];
    float* out = (float*)d_out;

    const int n   = in_sizes[1];
    const int rlo = n / NSEG;
    const int rem = n - rlo * NSEG;

    stats_k<<<NSEG, 256>>>((const float4*)x, y, n, rlo, rem);
    finalize_k<<<DDOM * 8, 256>>>(gamma, beta, NSEG);
    apply_k<<<NSEG, 256>>>((const float4*)x, (float4*)out, n, rlo, rem);
}

// round 11
// speedup vs baseline: 1.1138x; 1.1138x over previous
#include <cuda_runtime.h>
#include <cstdint>

#define FDIM   1024
#define FV     256            // float4 per row
#define DDOM   8
#define MAXN   16384
#define NSEG   296            // 2 full waves on 148 SMs
#define MAXR   64             // max rows per segment (56)
#define DEPTH  10             // stats cp.async depth (rows in flight)
#define RA     8              // rows per apply block
#define EPSV   1e-5f

// ---------------- scratch ----------------
__device__ float g_P[NSEG * DDOM * FDIM];     // partial sum(x)
__device__ float g_Q[NSEG * DDOM * FDIM];     // partial sum(x*x)
__device__ int   g_c[NSEG * DDOM];            // per-seg domain counts
__device__ unsigned char g_ydom[MAXN];        // decoded domain per row
__device__ float g_A[DDOM * FDIM];            // gamma * inv
__device__ float g_B[DDOM * FDIM];            // beta - mean * gamma * inv

// int64-vs-int32 y detection (odd 32-bit words all zero over 32 values)
__device__ __forceinline__ int detect64(const int* __restrict__ y) {
    const int4* p = (const int4*)y;
    int acc = 0;
#pragma unroll
    for (int i = 0; i < 8; i++) { int4 a = p[i]; acc |= a.y | a.w; }
    return acc == 0;
}

#define ACCUM(v)                                        \
    s1.x += v.x; s1.y += v.y; s1.z += v.z; s1.w += v.w; \
    s2.x = fmaf(v.x, v.x, s2.x);                        \
    s2.y = fmaf(v.y, v.y, s2.y);                        \
    s2.z = fmaf(v.z, v.z, s2.z);                        \
    s2.w = fmaf(v.w, v.w, s2.w);

// ---- K1: stats via cp.async pipeline over domain-sorted flat list (R9) ----
__global__ __launch_bounds__(256, 2)
void stats_k(const float4* __restrict__ x4, const int* __restrict__ yi,
             int n, int rlo, int rem) {
    __shared__ float4 buf[DEPTH][256];   // 40 KB ring
    __shared__ int flat[MAXR];           // row*FV, domain-sorted
    __shared__ int cnt[DDOM];
    __shared__ int fill[DDOM];

    const int tid  = threadIdx.x;
    const int b    = blockIdx.x;
    const int base = b * rlo + min(b, rem);
    const int nr   = min(rlo + (b < rem ? 1 : 0), n - base);

    if (tid < DDOM) cnt[tid] = 0;
    __syncthreads();

    if (tid < 32) {   // warp 0: deterministic 2-tile counting sort -> flat[]
        const int is64 = detect64(yi);
        const int r0 = base + tid;
        const int r1 = base + 32 + tid;
        const int da = (tid < nr)      ? (is64 ? yi[2 * r0] : yi[r0]) : -1;
        const int db = (32 + tid < nr) ? (is64 ? yi[2 * r1] : yi[r1]) : -1;
        const unsigned ma = __match_any_sync(0xffffffffu, da);
        if (da >= 0) {
            g_ydom[r0] = (unsigned char)da;
            if ((int)(__ffs(ma) - 1) == tid) cnt[da] = __popc(ma);
        }
        __syncwarp();
        const unsigned mb = __match_any_sync(0xffffffffu, db);
        if (db >= 0) {
            g_ydom[r1] = (unsigned char)db;
            if ((int)(__ffs(mb) - 1) == tid) cnt[db] += __popc(mb);
        }
        __syncwarp();
        if (tid == 0) {
            int run = 0;
#pragma unroll
            for (int d = 0; d < DDOM; d++) { fill[d] = run; run += cnt[d]; }
        }
        __syncwarp();
        const int ra = __popc(ma & ((1u << tid) - 1u));
        if (da >= 0) flat[fill[da] + ra] = r0 * FV;
        __syncwarp();
        if (da >= 0 && (int)(__ffs(ma) - 1) == tid) fill[da] += __popc(ma);
        __syncwarp();
        const int rb = __popc(mb & ((1u << tid) - 1u));
        if (db >= 0) flat[fill[db] + rb] = r1 * FV;
    }
    __syncthreads();

    uint32_t sbuf;
    asm("{ .reg .u64 t; cvta.to.shared.u64 t, %1; cvt.u32.u64 %0, t; }"
        : "=r"(sbuf) : "l"(buf));
    const char* xb = (const char*)x4;
    const uint32_t myoff = tid * 16;

#define ISSUE(k) do {                                                        \
        uint32_t _da = sbuf + ((k) % DEPTH) * 4096 + myoff;                  \
        const void* _g = xb + ((size_t)(flat[(k)] + tid) << 4);              \
        asm volatile("cp.async.cg.shared.global [%0], [%1], 16;"             \
                     :: "r"(_da), "l"(_g) : "memory");                       \
        asm volatile("cp.async.commit_group;" ::: "memory");                 \
    } while (0)

    const int np = min(DEPTH, nr);
    for (int k = 0; k < np; k++) ISSUE(k);
    int issued = np;
    int i = 0;

#pragma unroll
    for (int d = 0; d < DDOM; d++) {
        const int nd = cnt[d];
        float4 s1 = make_float4(0.f, 0.f, 0.f, 0.f);
        float4 s2 = make_float4(0.f, 0.f, 0.f, 0.f);
        for (int k = 0; k < nd; k++, i++) {
            if (issued < nr) {
                asm volatile("cp.async.wait_group %0;" :: "n"(DEPTH - 1) : "memory");
            } else {
                asm volatile("cp.async.wait_group 0;" ::: "memory");
            }
            float4 v = buf[i % DEPTH][tid];
            if (issued < nr) { ISSUE(issued); issued++; }
            ACCUM(v);
        }
        const size_t o = ((size_t)b * DDOM + d) * FV + tid;
        ((float4*)g_P)[o] = s1;
        ((float4*)g_Q)[o] = s2;
    }
    if (tid < DDOM) g_c[b * DDOM + tid] = cnt[tid];
#undef ISSUE
}

// ---- K2: fold segments -> A/B. grid = 64 blocks (8 dom x 8 f4-slices). ----
__global__ __launch_bounds__(256)
void finalize_k(const float* __restrict__ gamma, const float* __restrict__ beta,
                int nseg) {
    __shared__ float4 smP[8][32];
    __shared__ float4 smQ[8][32];
    __shared__ int    scnt[256];
    const int tid  = threadIdx.x;
    const int d    = blockIdx.x >> 3;
    const int fs   = blockIdx.x & 7;
    const int w    = tid >> 5, lane = tid & 31;
    const int posIdx = fs * 32 + lane;

    {
        int c = 0;
        for (int s = tid; s < nseg; s += 256) c += g_c[s * DDOM + d];
        scnt[tid] = c;
    }

    const float4* P4 = (const float4*)g_P;
    const float4* Q4 = (const float4*)g_Q;
    float4 ap = make_float4(0.f, 0.f, 0.f, 0.f);
    float4 aq = make_float4(0.f, 0.f, 0.f, 0.f);
    int s = w;
    for (; s + 8 < nseg; s += 16) {
        const size_t o0 = ((size_t)s * DDOM + d) * FV + posIdx;
        const size_t o1 = ((size_t)(s + 8) * DDOM + d) * FV + posIdx;
        float4 p0 = P4[o0], q0 = Q4[o0];
        float4 p1 = P4[o1], q1 = Q4[o1];
        ap.x += p0.x + p1.x; ap.y += p0.y + p1.y;
        ap.z += p0.z + p1.z; ap.w += p0.w + p1.w;
        aq.x += q0.x + q1.x; aq.y += q0.y + q1.y;
        aq.z += q0.z + q1.z; aq.w += q0.w + q1.w;
    }
    for (; s < nseg; s += 8) {
        const size_t o = ((size_t)s * DDOM + d) * FV + posIdx;
        float4 p = P4[o], q = Q4[o];
        ap.x += p.x; ap.y += p.y; ap.z += p.z; ap.w += p.w;
        aq.x += q.x; aq.y += q.y; aq.z += q.z; aq.w += q.w;
    }
    smP[w][lane] = ap;
    smQ[w][lane] = aq;
    __syncthreads();

    for (int off = 128; off > 0; off >>= 1) {
        if (tid < off) scnt[tid] += scnt[tid + off];
        __syncthreads();
    }
    const float c = (float)scnt[0];

    if (w == 0) {
        float4 s1 = smP[0][lane], s2 = smQ[0][lane];
#pragma unroll
        for (int ww = 1; ww < 8; ww++) {
            float4 p = smP[ww][lane], q = smQ[ww][lane];
            s1.x += p.x; s1.y += p.y; s1.z += p.z; s1.w += p.w;
            s2.x += q.x; s2.y += q.y; s2.z += q.z; s2.w += q.w;
        }
        const int o = d * FDIM + posIdx * 4;
        float4 A, Bv;
        if (c > 1.5f) {
            const float rc = 1.0f / c;
            float4 g  = *(const float4*)(gamma + o);
            float4 be = *(const float4*)(beta + o);
            float mx = s1.x * rc, my = s1.y * rc, mz = s1.z * rc, mw = s1.w * rc;
            float vx = fmaf(-mx, mx, s2.x * rc);
            float vy = fmaf(-my, my, s2.y * rc);
            float vz = fmaf(-mz, mz, s2.z * rc);
            float vw = fmaf(-mw, mw, s2.w * rc);
            A.x = g.x * rsqrtf(vx + EPSV);
            A.y = g.y * rsqrtf(vy + EPSV);
            A.z = g.z * rsqrtf(vz + EPSV);
            A.w = g.w * rsqrtf(vw + EPSV);
            Bv.x = fmaf(-mx, A.x, be.x);
            Bv.y = fmaf(-my, A.y, be.y);
            Bv.z = fmaf(-mz, A.z, be.z);
            Bv.w = fmaf(-mw, A.w, be.w);
        } else if (c > 0.5f) {   // single-sample domain: out = x
            A  = make_float4(1.f, 1.f, 1.f, 1.f);
            Bv = make_float4(0.f, 0.f, 0.f, 0.f);
        } else {                 // empty domain (unused)
            A  = make_float4(0.f, 0.f, 0.f, 0.f);
            Bv = make_float4(0.f, 0.f, 0.f, 0.f);
        }
        *(float4*)(g_A + o) = A;
        *(float4*)(g_B + o) = Bv;
    }
}

// ---- K3: out = A[d]*x + B[d]; 8 v-loads issued before consumption ----
__global__ __launch_bounds__(256)
void apply_k(const float4* __restrict__ x4, float4* __restrict__ o4, int n) {
    __shared__ int sd[RA];
    const int tid = threadIdx.x;
    const int r0  = blockIdx.x * RA;

    if (tid < RA) {
        const int r = r0 + tid;
        sd[tid] = (r < n) ? (int)g_ydom[r] : 0;
    }
    __syncthreads();

    const float4* A4 = (const float4*)g_A;
    const float4* B4 = (const float4*)g_B;

    if (r0 + RA <= n) {
        const float4* p = x4 + (size_t)r0 * FV + tid;
        float4 v[RA];
#pragma unroll
        for (int j = 0; j < RA; j++) v[j] = __ldcs(p + j * FV);   // MLP 8
#pragma unroll
        for (int j = 0; j < RA; j++) {
            const int dd = sd[j];
            const float4 a = __ldg(A4 + dd * FV + tid);
            const float4 b = __ldg(B4 + dd * FV + tid);
            float4 w;
            w.x = fmaf(v[j].x, a.x, b.x);
            w.y = fmaf(v[j].y, a.y, b.y);
            w.z = fmaf(v[j].z, a.z, b.z);
            w.w = fmaf(v[j].w, a.w, b.w);
            __stcs(o4 + (size_t)(r0 + j) * FV + tid, w);
        }
    } else {
        for (int j = 0; j < RA; j++) {
            const int rr = r0 + j;
            if (rr >= n) break;
            const int dd = sd[j];
            float4 v = __ldcs(x4 + (size_t)rr * FV + tid);
            float4 a = __ldg(A4 + dd * FV + tid);
            float4 b = __ldg(B4 + dd * FV + tid);
            float4 w;
            w.x = fmaf(v.x, a.x, b.x); w.y = fmaf(v.y, a.y, b.y);
            w.z = fmaf(v.z, a.z, b.z); w.w = fmaf(v.w, a.w, b.w);
            __stcs(o4 + (size_t)rr * FV + tid, w);
        }
    }
}

extern "C" void kernel_launch(void* const* d_in, const int* in_sizes, int n_in,
                              void* d_out, int out_size) {
    const float* x     = (const float*)d_in[0];
    const int*   y     = (const int*)d_in[1];
    const float* gamma = (const float*)d_in[2];
    const float* beta  = (const float*)d_in[3];
    float* out = (float*)d_out;

    const int n   = in_sizes[1];
    const int rlo = n / NSEG;
    const int rem = n - rlo * NSEG;

    stats_k<<<NSEG, 256>>>((const float4*)x, y, n, rlo, rem);
    finalize_k<<<DDOM * 8, 256>>>(gamma, beta, NSEG);
    apply_k<<<(n + RA - 1) / RA, 256>>>((const float4*)x, (float4*)out, n);
}